// round 5
// baseline (speedup 1.0000x reference)
#include <cuda_runtime.h>

// BlinnPhongShaderEnvMap: H=512, W=512 pixels, K=128 lights.
// Inputs (metadata order):
//  0 pixel_normals    (H,W,3) f32   786432
//  1 pixel_directions (H,W,3) f32   786432
//  2 camera_position  (3,)    f32   3
//  3 light_directions (K,3)   f32   384  (unit vectors)
//  4 light_colors     (K,3)   f32   384
//  5 shininess        (1,)    f32
//  6 kd               (1,)    f32
//  7 ks               (1,)    f32
// Output: concat(colors (H,W,3), n (H,W,3)) = 1572864 f32

#define NPIX (512 * 512)
#define K 128

__global__ __launch_bounds__(256)
void blinn_phong_kernel(const float* __restrict__ pn,
                        const float* __restrict__ pd,
                        const float* __restrict__ cam,
                        const float* __restrict__ ld,
                        const float* __restrict__ lc,
                        const float* __restrict__ shin_p,
                        const float* __restrict__ kd_p,
                        const float* __restrict__ ks_p,
                        float* __restrict__ out) {
    __shared__ float sL[K * 3];
    __shared__ float sC[K * 3];

    const int tid = threadIdx.x;
    for (int i = tid; i < K * 3; i += blockDim.x) {
        sL[i] = ld[i];
        sC[i] = lc[i];
    }
    __syncthreads();

    const int p = blockIdx.x * blockDim.x + tid;
    if (p >= NPIX) return;

    // --- load + normalize pixel normal (matches F.normalize eps=1e-6) ---
    float nx = pn[3 * p + 0];
    float ny = pn[3 * p + 1];
    float nz = pn[3 * p + 2];
    {
        float nn = nx * nx + ny * ny + nz * nz;
        // 1/max(sqrt(nn), 1e-6) == rsqrt(max(nn, 1e-12))
        float inv = rsqrtf(fmaxf(nn, 1e-12f));
        nx *= inv; ny *= inv; nz *= inv;
    }

    // --- view direction v = normalize(cam - pixel_direction) ---
    float vx = cam[0] - pd[3 * p + 0];
    float vy = cam[1] - pd[3 * p + 1];
    float vz = cam[2] - pd[3 * p + 2];
    {
        float vv = vx * vx + vy * vy + vz * vz;
        float inv = rsqrtf(fmaxf(vv, 1e-12f));
        vx *= inv; vy *= inv; vz *= inv;
    }

    const float nv = nx * vx + ny * vy + nz * vz;
    const float shin = shin_p[0];
    const float kdv  = kd_p[0];
    const float ksv  = ks_p[0];

    float dr = 0.f, dg = 0.f, db = 0.f;   // diffuse accum
    float sr = 0.f, sg = 0.f, sbl = 0.f;  // specular accum

#pragma unroll 16
    for (int k = 0; k < K; k++) {
        const float lx = sL[3 * k + 0];
        const float ly = sL[3 * k + 1];
        const float lz = sL[3 * k + 2];

        const float nl = nx * lx + ny * ly + nz * lz;
        const float vl = vx * lx + vy * ly + vz * lz;

        // diffuse term: clip(n.L, 0, 1) -> single .SAT op
        const float d = __saturatef(nl);

        // specular: dot(n, normalize(v + L)) = (nv + nl) * rsqrt(|v+L|^2)
        // |v+L|^2 = 2 + 2*v.L (both unit). F.normalize eps handling:
        // divide by max(|v+L|, 1e-6) == * rsqrt(max(|v+L|^2, 1e-12)).
        const float h2  = 2.f + 2.f * vl;
        const float rin = rsqrtf(fmaxf(h2, 1e-12f));
        float s = __saturatef((nv + nl) * rin);
        s = __powf(s, shin);   // exp2(shin*log2(s)); log2(0)=-inf -> 0, correct

        const float cr = sC[3 * k + 0];
        const float cg = sC[3 * k + 1];
        const float cb = sC[3 * k + 2];

        dr += cr * d;  dg += cg * d;  db += cb * d;
        sr += cr * s;  sg += cg * s;  sbl += cb * s;
    }

    // norm_factor = (shin+2) / (4*(2 - exp(-shin/2)))
    const float nf = (shin + 2.f) / (4.f * (2.f - __expf(-0.5f * shin)));
    const float kss = nf * ksv;

    // output 0: colors
    out[3 * p + 0] = kdv * dr + kss * sr;
    out[3 * p + 1] = kdv * dg + kss * sg;
    out[3 * p + 2] = kdv * db + kss * sbl;

    // output 1: normalized normals
    out[3 * NPIX + 3 * p + 0] = nx;
    out[3 * NPIX + 3 * p + 1] = ny;
    out[3 * NPIX + 3 * p + 2] = nz;
}

extern "C" void kernel_launch(void* const* d_in, const int* in_sizes, int n_in,
                              void* d_out, int out_size) {
    const float* pn   = (const float*)d_in[0];
    const float* pd   = (const float*)d_in[1];
    const float* cam  = (const float*)d_in[2];
    const float* ld   = (const float*)d_in[3];
    const float* lc   = (const float*)d_in[4];
    const float* shin = (const float*)d_in[5];
    const float* kd   = (const float*)d_in[6];
    const float* ks   = (const float*)d_in[7];
    float* out = (float*)d_out;

    const int threads = 256;
    const int blocks = (NPIX + threads - 1) / threads;
    blinn_phong_kernel<<<blocks, threads>>>(pn, pd, cam, ld, lc, shin, kd, ks, out);
}